// round 16
// baseline (speedup 1.0000x reference)
#include <cuda_runtime.h>
#include <math.h>
#include <stdint.h>

#define BATCH  2048
#define NROWS  512
#define MDIM   64
#define HDIM   100
#define INDIM  64
#define OUTDIM 64
#define EPS    1e-8f

#define SCR_STRIDE 288
__device__ float g_scratch[(size_t)BATCH * SCR_STRIDE];

__device__ __forceinline__ float softplus_f(float x) {
    return (x > 20.f) ? x : log1pf(expf(x));
}
__device__ __forceinline__ float sigmoid_f(float x) {
    return 1.f / (1.f + expf(-x));
}

__device__ __forceinline__ void cp_async16(void* smem_dst, const void* gmem_src) {
    unsigned s = (unsigned)__cvta_generic_to_shared(smem_dst);
    asm volatile("cp.async.cg.shared.global [%0], [%1], 16;\n" :: "r"(s), "l"(gmem_src));
}
#define CP_COMMIT()  asm volatile("cp.async.commit_group;\n")

// ---------------------------------------------------------------------------
// Kernel 1: head parameters (R5-proven config, unchanged).
// ---------------------------------------------------------------------------
#define P_CW   0
#define P_WH   6400
#define P_RH   13400
#define P_WE   20400
#define P_XS   33200
#define P_HS   34288
#define P_PS   36288
#define P_TOT  40640

__global__ __launch_bounds__(576) void ntm_params_kernel(
    const float* __restrict__ x,  const float* __restrict__ cW,  const float* __restrict__ cb,
    const float* __restrict__ whW, const float* __restrict__ whb,
    const float* __restrict__ weW, const float* __restrict__ web,
    const float* __restrict__ rhW, const float* __restrict__ rhb)
{
    extern __shared__ __align__(16) float psm[];
    float* xs = psm + P_XS;
    float* hs = psm + P_HS;
    float* ps = psm + P_PS;

    const int tid = threadIdx.x;
    const int b0  = blockIdx.x * 16;

    {
        float4* d = (float4*)(psm + P_CW);
        const float4* s = (const float4*)cW;
        for (int k = tid; k < 1600; k += 576) cp_async16(&d[k], &s[k]);
        CP_COMMIT();
    }
    {
        float4* d; const float4* s;
        d = (float4*)(psm + P_WH); s = (const float4*)whW;
        for (int k = tid; k < 1750; k += 576) cp_async16(&d[k], &s[k]);
        d = (float4*)(psm + P_RH); s = (const float4*)rhW;
        for (int k = tid; k < 1750; k += 576) cp_async16(&d[k], &s[k]);
        d = (float4*)(psm + P_WE); s = (const float4*)weW;
        for (int k = tid; k < 3200; k += 576) cp_async16(&d[k], &s[k]);
        CP_COMMIT();
    }

    for (int idx = tid; idx < 16 * 64; idx += 576) {
        int b = idx >> 6, i = idx & 63;
        xs[i * 17 + b] = x[(size_t)(b0 + b) * 64 + i];
    }
    asm volatile("cp.async.wait_group 1;\n");
    __syncthreads();

    for (int idx = tid; idx < 16 * 100; idx += 576) {
        int j = idx % 100, b = idx / 100;
        float acc = cb[j];
        #pragma unroll 8
        for (int i = 0; i < 64; i++) acc = fmaf(xs[i * 17 + b], psm[P_CW + i * 100 + j], acc);
        hs[j * 20 + b] = acc;
    }
    asm volatile("cp.async.wait_group 0;\n");
    __syncthreads();

    {
        int j = -1, bo = 0;
        if (tid < 268)                        { j = tid;       bo = 0; }
        else if (tid >= 288 && tid < 556)     { j = tid - 288; bo = 8; }
        if (j >= 0) {
            const float* W; int stride, jj; float bj;
            if (j < 70)       { W = psm + P_WH; stride = 70;  jj = j;       bj = whb[jj]; }
            else if (j < 140) { W = psm + P_RH; stride = 70;  jj = j - 70;  bj = rhb[jj]; }
            else              { W = psm + P_WE; stride = 128; jj = j - 140; bj = web[jj]; }

            float acc[8];
            #pragma unroll
            for (int b = 0; b < 8; b++) acc[b] = bj;

            #pragma unroll 4
            for (int i = 0; i < HDIM; i++) {
                float w = W[i * stride + jj];
                const float4* hv = (const float4*)(hs + i * 20 + bo);
                float4 h0 = hv[0], h1 = hv[1];
                acc[0] = fmaf(h0.x, w, acc[0]);  acc[1] = fmaf(h0.y, w, acc[1]);
                acc[2] = fmaf(h0.z, w, acc[2]);  acc[3] = fmaf(h0.w, w, acc[3]);
                acc[4] = fmaf(h1.x, w, acc[4]);  acc[5] = fmaf(h1.y, w, acc[5]);
                acc[6] = fmaf(h1.z, w, acc[6]);  acc[7] = fmaf(h1.w, w, acc[7]);
            }
            #pragma unroll
            for (int b = 0; b < 8; b++) ps[(bo + b) * 272 + j] = acc[b];
        }
    }
    __syncthreads();

    for (int idx = tid; idx < 16 * 128; idx += 576) {
        int b = idx >> 7, j = idx & 127;
        float v = ps[b * 272 + 140 + j];
        float* scr = g_scratch + (size_t)(b0 + b) * SCR_STRIDE;
        if (j < 64) scr[128 + j]        = sigmoid_f(v);
        else        scr[192 + (j - 64)] = v;
    }
    for (int idx = tid; idx < 16 * 64; idx += 576) {
        int b = idx >> 6, j = idx & 63;
        float* scr = g_scratch + (size_t)(b0 + b) * SCR_STRIDE;
        scr[j]      = ps[b * 272 + j];
        scr[64 + j] = ps[b * 272 + 70 + j];
    }
    if (tid < 16) {
        const float* pw = ps + tid * 272;
        const float* pr = pw + 70;
        float* scr = g_scratch + (size_t)(b0 + tid) * SCR_STRIDE + 256;
        float ssw = 0.f, ssr = 0.f;
        #pragma unroll 8
        for (int j = 0; j < 64; j++) { ssw = fmaf(pw[j], pw[j], ssw); ssr = fmaf(pr[j], pr[j], ssr); }

        scr[0] = softplus_f(pw[64]);
        scr[1] = sigmoid_f(pw[65]);
        float m  = fmaxf(pw[66], fmaxf(pw[67], pw[68]));
        float e0 = expf(pw[66] - m), e1 = expf(pw[67] - m), e2 = expf(pw[68] - m);
        float s  = e0 + e1 + e2;
        scr[2] = e0 / s; scr[3] = e1 / s; scr[4] = e2 / s;
        scr[5] = 1.f + softplus_f(pw[69]);
        scr[6] = fmaxf(sqrtf(ssw), EPS);

        scr[7] = softplus_f(pr[64]);
        scr[8] = sigmoid_f(pr[65]);
        m  = fmaxf(pr[66], fmaxf(pr[67], pr[68]));
        e0 = expf(pr[66] - m); e1 = expf(pr[67] - m); e2 = expf(pr[68] - m);
        s  = e0 + e1 + e2;
        scr[9] = e0 / s; scr[10] = e1 / s; scr[11] = e2 / s;
        scr[12] = 1.f + softplus_f(pr[69]);
        scr[13] = fmaxf(sqrtf(ssr), EPS);
    }
}

// ---------------------------------------------------------------------------
__device__ __forceinline__ float blockSum512(float v, float* red16) {
    #pragma unroll
    for (int o = 16; o > 0; o >>= 1) v += __shfl_xor_sync(0xffffffffu, v, o);
    if ((threadIdx.x & 31) == 0) red16[threadIdx.x >> 5] = v;
    __syncthreads();
    float s = 0.f;
    #pragma unroll
    for (int i = 0; i < 16; i++) s += red16[i];
    return s;
}

// ---------------------------------------------------------------------------
// Kernel 2: main. One CTA/batch, 512 threads, occ 3.
// Pass 1: BARRIER-FREE thread-private cp.async pipeline. Each thread copies
//   and consumes exactly its own 2 float4s per tile (row tid>>3, cols cg,cg+8),
//   so cp.async.wait_group alone orders producer->consumer and buffer reuse is
//   thread-private. Linear layout, conflict-free per quarter-warp. No swizzle.
// Addressing: smem attn, no-max softmax, 1-barrier sums, __expf/__powf.
// Pass 2: direct coalesced float4 global read (L2-hot) + __stcs write.
// ---------------------------------------------------------------------------
#define SMEM_FLOATS (8192 + 4096 + 256 + 1536 + 80 + 16 + 64 + 16 + 1024)

__global__ __launch_bounds__(512, 3) void ntm_main_kernel(
    const float* __restrict__ memory, const float* __restrict__ read_attn,
    const float* __restrict__ write_attn, const float* __restrict__ oW,
    const float* __restrict__ ob,
    float* __restrict__ out_out, float* __restrict__ out_mem2,
    float* __restrict__ out_wr,  float* __restrict__ out_ww)
{
    extern __shared__ __align__(16) float sm[];
    float4* bufA  = (float4*)sm;
    float4* bufB  = bufA + 1024;
    float*  mom   = sm + 8192;
    float*  c_kw  = sm + 12288;
    float*  c_kr  = c_kw + 64;
    float*  c_e   = c_kr + 64;
    float*  c_a   = c_e  + 64;
    float*  ww_s  = c_a  + 64;
    float*  wr_s  = ww_s + 512;
    float*  wg_s  = wr_s + 512;
    float*  red   = wg_s + 512;
    float*  scal  = red  + 80;
    float*  rs    = scal + 16;
    float*  sc2   = rs   + 64;
    float*  wa_s  = sc2  + 16;
    float*  ra_s  = wa_s + 512;

    const int tid = threadIdx.x;
    const int b   = blockIdx.x;
    const float* mbase = memory + (size_t)b * NROWS * MDIM;
    const float4* mb4  = (const float4*)mbase;

    const int row_l = tid >> 3;           // 0..63
    const int cg    = tid & 7;            // 0..7
    const int sA = row_l * 16 + cg;       // thread-private slot A
    const int sB = row_l * 16 + 8 + cg;   // thread-private slot B

    // ---- prologue: tiles 0,1 via thread-private cp.async (+attn) --------------
    {
        cp_async16(&bufA[sA], &mb4[sA]);
        cp_async16(&bufA[sB], &mb4[sB]);
        if (tid < 128)
            cp_async16(((float4*)wa_s) + tid, ((const float4*)(write_attn + (size_t)b * 512)) + tid);
        else if (tid < 256)
            cp_async16(((float4*)ra_s) + (tid - 128), ((const float4*)(read_attn + (size_t)b * 512)) + (tid - 128));
        CP_COMMIT();                        // group: tile 0 (+attn)
        cp_async16(&bufB[sA], &mb4[1024 + sA]);
        cp_async16(&bufB[sB], &mb4[1024 + sB]);
        CP_COMMIT();                        // group: tile 1
    }

    // ---- coefficients (needs one barrier; attn arrives via wait_group later) --
    {
        const float* scr = g_scratch + (size_t)b * SCR_STRIDE;
        if (tid < 64) {
            c_kw[tid] = scr[tid];
            c_kr[tid] = scr[64 + tid];
            c_e[tid]  = scr[128 + tid];
            c_a[tid]  = scr[192 + tid];
        } else if (tid < 80) {
            scal[tid - 64] = scr[256 + (tid - 64)];
        }
    }
    __syncthreads();
    if (tid < 32) {
        float ka = c_kr[tid] * c_a[tid] + c_kr[tid + 32] * c_a[tid + 32];
        float aa = c_a[tid]  * c_a[tid] + c_a[tid + 32]  * c_a[tid + 32];
        #pragma unroll
        for (int o = 16; o > 0; o >>= 1) {
            ka += __shfl_xor_sync(0xffffffffu, ka, o);
            aa += __shfl_xor_sync(0xffffffffu, aa, o);
        }
        if (tid == 0) { sc2[0] = ka; sc2[1] = aa; }
    }

    // ---- pass 1: BARRIER-FREE moments (8 tiles of 64 rows) ---------------------
    const float4* kw4 = (const float4*)c_kw;
    const float4* kr4 = (const float4*)c_kr;
    const float4* e4  = (const float4*)c_e;
    const float4* a4  = (const float4*)c_a;
    const float4 kwA = kw4[cg],     krA = kr4[cg],     eeA = e4[cg],     aaA = a4[cg];
    const float4 kwB = kw4[cg + 8], krB = kr4[cg + 8], eeB = e4[cg + 8], aaB = a4[cg + 8];

    #pragma unroll 1
    for (int tt = 0; tt < 8; tt++) {
        if (tt < 7) { asm volatile("cp.async.wait_group 1;\n"); }
        else        { asm volatile("cp.async.wait_group 0;\n"); }
        // no __syncthreads: this thread only reads slots it wrote itself

        const float4* bt = (tt & 1) ? bufB : bufA;
        float4 v1 = bt[sA];
        float4 v2 = bt[sB];

        // m[0]=d0 m[1]=q0 m[2]=d1 m[3]=d2 m[4]=p1 m[5]=p2 m[6]=t1 m[7]=t2
        float m[8] = {0.f, 0.f, 0.f, 0.f, 0.f, 0.f, 0.f, 0.f};
        #define ACC8(v, KW, KR, EE, AA)  do { \
            float vv = (v), ev = (EE) * vv; \
            m[0] = fmaf((KW), vv, m[0]);  m[2] = fmaf((KR), vv, m[2]);  m[6] = fmaf((AA), vv, m[6]); \
            m[1] = fmaf(vv, vv, m[1]);    m[4] = fmaf(vv, ev, m[4]);    m[5] = fmaf(ev, ev, m[5]); \
            m[3] = fmaf((KR), ev, m[3]);  m[7] = fmaf((AA), ev, m[7]);  } while (0)
        ACC8(v1.x, kwA.x, krA.x, eeA.x, aaA.x);
        ACC8(v1.y, kwA.y, krA.y, eeA.y, aaA.y);
        ACC8(v1.z, kwA.z, krA.z, eeA.z, aaA.z);
        ACC8(v1.w, kwA.w, krA.w, eeA.w, aaA.w);
        ACC8(v2.x, kwB.x, krB.x, eeB.x, aaB.x);
        ACC8(v2.y, kwB.y, krB.y, eeB.y, aaB.y);
        ACC8(v2.z, kwB.z, krB.z, eeB.z, aaB.z);
        ACC8(v2.w, kwB.w, krB.w, eeB.w, aaB.w);
        #undef ACC8

        // refill the buffer just consumed (thread-private slots) BEFORE the
        // shfl reduction, to get the load in flight early.
        if (tt + 2 < 8) {
            float4* dst = (tt & 1) ? bufB : bufA;
            const float4* src = mb4 + (size_t)(tt + 2) * 1024;
            cp_async16(&dst[sA], &src[sA]);
            cp_async16(&dst[sB], &src[sB]);
        }
        CP_COMMIT();   // uniform group count across threads (empty group ok at tail)

        // 7-shfl halving exchange: lane cg ends with sum of moment cg
        if (cg & 4) {
            float t;
            t = m[0]; m[0] = m[4]; m[4] = t;
            t = m[1]; m[1] = m[5]; m[5] = t;
            t = m[2]; m[2] = m[6]; m[6] = t;
            t = m[3]; m[3] = m[7]; m[7] = t;
        }
        m[0] += __shfl_xor_sync(0xffffffffu, m[4], 4);
        m[1] += __shfl_xor_sync(0xffffffffu, m[5], 4);
        m[2] += __shfl_xor_sync(0xffffffffu, m[6], 4);
        m[3] += __shfl_xor_sync(0xffffffffu, m[7], 4);
        if (cg & 2) {
            float t;
            t = m[0]; m[0] = m[2]; m[2] = t;
            t = m[1]; m[1] = m[3]; m[3] = t;
        }
        m[0] += __shfl_xor_sync(0xffffffffu, m[2], 2);
        m[1] += __shfl_xor_sync(0xffffffffu, m[3], 2);
        if (cg & 1) {
            float t = m[0]; m[0] = m[1]; m[1] = t;
        }
        m[0] += __shfl_xor_sync(0xffffffffu, m[1], 1);

        mom[(tt * 64 + row_l) * 8 + cg] = m[0];
    }
    __syncthreads();   // publish mom + attn (+ all cp.async long since drained)

    // ---- addressing -------------------------------------------------------------
    const int n = tid;
    float4 m0 = ((const float4*)mom)[n * 2];
    float4 m1 = ((const float4*)mom)[n * 2 + 1];
    const float d0 = m0.x, q0 = m0.y, d1 = m0.z, d2 = m0.w;
    const float p1 = m1.x, p2 = m1.y, t1 = m1.z, t2 = m1.w;

    const float beta_w = scal[0], gate_w = scal[1], shw0 = scal[2], shw1 = scal[3],
                shw2 = scal[4], gamma_w = scal[5], kn_w = scal[6];
    const float beta_r = scal[7], gate_r = scal[8], shr0 = scal[9], shr1 = scal[10],
                shr2 = scal[11], gamma_r = scal[12], kn_r = scal[13];
    const float ka = sc2[0], aa = sc2[1];

    // write head (no max-subtraction: |score| <= beta, safe in fp32)
    float mn = fmaxf(sqrtf(q0), EPS);
    float ex = __expf(beta_w * d0 / (kn_w * mn));
    float sum = blockSum512(ex, red);
    float wc  = ex / sum;
    float wgv = gate_w * wc + (1.f - gate_w) * wa_s[n];
    wg_s[n] = wgv;
    __syncthreads();
    float tw  = shw2 * wg_s[(n + 511) & 511] + shw1 * wgv + shw0 * wg_s[(n + 1) & 511];
    float twg = __powf(tw, gamma_w);
    float tsum = blockSum512(twg, red + 16);
    float ww = twg / (EPS + tsum);
    ww_s[n] = ww;
    __stcs(out_ww + (size_t)b * NROWS + n, ww);

    // read head on virtual mem2
    float dot2 = d1 - ww * d2 + ww * ka;
    float ss2  = q0 - 2.f * ww * p1 + ww * ww * p2
               + 2.f * ww * t1 - 2.f * ww * ww * t2 + ww * ww * aa;
    float mn2 = fmaxf(sqrtf(fmaxf(ss2, 0.f)), EPS);
    float ex2 = __expf(beta_r * dot2 / (kn_r * mn2));
    float sum2 = blockSum512(ex2, red + 32);
    float wc2  = ex2 / sum2;
    float wgv2 = gate_r * wc2 + (1.f - gate_r) * ra_s[n];
    wg_s[n] = wgv2;
    __syncthreads();
    float tw2  = shr2 * wg_s[(n + 511) & 511] + shr1 * wgv2 + shr0 * wg_s[(n + 1) & 511];
    float twg2 = __powf(tw2, gamma_r);
    float tsum2 = blockSum512(twg2, red + 48);
    float wr = twg2 / (EPS + tsum2);
    wr_s[n] = wr;
    __stcs(out_wr + (size_t)b * NROWS + n, wr);

    float cwr = blockSum512(wr * ww, red + 64);  // barrier also publishes ww_s/wr_s

    // ---- pass 2: direct global mem2 + S1/S2 (L2-hot reads) ----------------------
    float* s1p = mom;
    float* s2p = mom + 2048;
    {
        const int m4 = tid & 15;
        const int g  = tid >> 4;
        const float4 em = ((const float4*)c_e)[m4];
        const float4 am = ((const float4*)c_a)[m4];
        float4* m2b4 = (float4*)(out_mem2 + (size_t)b * NROWS * MDIM);

        float4 s1 = make_float4(0.f, 0.f, 0.f, 0.f);
        float4 s2 = make_float4(0.f, 0.f, 0.f, 0.f);
        #pragma unroll 4
        for (int i = 0; i < 16; i++) {
            int nn = i * 32 + g;
            float4 v = __ldg(&mb4[nn * 16 + m4]);
            float wwn = ww_s[nn], wrn = wr_s[nn];
            float4 m2;
            m2.x = fmaf(v.x, 1.f - wwn * em.x, wwn * am.x);
            m2.y = fmaf(v.y, 1.f - wwn * em.y, wwn * am.y);
            m2.z = fmaf(v.z, 1.f - wwn * em.z, wwn * am.z);
            m2.w = fmaf(v.w, 1.f - wwn * em.w, wwn * am.w);
            __stcs(&m2b4[nn * 16 + m4], m2);
            float wrw = wrn * wwn;
            s1.x = fmaf(wrn, v.x, s1.x);  s2.x = fmaf(wrw, v.x, s2.x);
            s1.y = fmaf(wrn, v.y, s1.y);  s2.y = fmaf(wrw, v.y, s2.y);
            s1.z = fmaf(wrn, v.z, s1.z);  s2.z = fmaf(wrw, v.z, s2.z);
            s1.w = fmaf(wrn, v.w, s1.w);  s2.w = fmaf(wrw, v.w, s2.w);
        }
        ((float4*)s1p)[tid] = s1;
        ((float4*)s2p)[tid] = s2;
    }
    __syncthreads();

    if (tid < 64) {
        float r1 = 0.f, r2 = 0.f;
        #pragma unroll
        for (int g = 0; g < 32; g++) { r1 += s1p[g * 64 + tid]; r2 += s2p[g * 64 + tid]; }
        rs[tid] = r1 - c_e[tid] * r2 + cwr * c_a[tid];
    }
    __syncthreads();

    if (tid < 64) {
        float acc = ob[tid];
        #pragma unroll 8
        for (int m = 0; m < 64; m++) acc = fmaf(rs[m], oW[m * 64 + tid], acc);
        out_out[(size_t)b * OUTDIM + tid] = sigmoid_f(acc);
    }
}

// ---------------------------------------------------------------------------
extern "C" void kernel_launch(void* const* d_in, const int* in_sizes, int n_in,
                              void* d_out, int out_size)
{
    const float* x          = (const float*)d_in[0];
    const float* memory     = (const float*)d_in[1];
    const float* read_attn  = (const float*)d_in[2];
    const float* write_attn = (const float*)d_in[3];
    const float* cW         = (const float*)d_in[4];
    const float* cb         = (const float*)d_in[5];
    const float* oW         = (const float*)d_in[6];
    const float* ob         = (const float*)d_in[7];
    const float* whW        = (const float*)d_in[8];
    const float* whb        = (const float*)d_in[9];
    const float* weW        = (const float*)d_in[10];
    const float* web        = (const float*)d_in[11];
    const float* rhW        = (const float*)d_in[12];
    const float* rhb        = (const float*)d_in[13];

    float* out_out  = (float*)d_out;
    float* out_mem2 = out_out  + (size_t)BATCH * OUTDIM;
    float* out_wr   = out_mem2 + (size_t)BATCH * NROWS * MDIM;
    float* out_ww   = out_wr   + (size_t)BATCH * NROWS;

    const int smemP = P_TOT * (int)sizeof(float);
    const int smemB = SMEM_FLOATS * (int)sizeof(float);
    cudaFuncSetAttribute(ntm_params_kernel,
                         cudaFuncAttributeMaxDynamicSharedMemorySize, smemP);
    cudaFuncSetAttribute(ntm_main_kernel,
                         cudaFuncAttributeMaxDynamicSharedMemorySize, smemB);

    ntm_params_kernel<<<BATCH / 16, 576, smemP>>>(x, cW, cb, whW, whb, weW, web, rhW, rhb);
    ntm_main_kernel<<<BATCH, 512, smemB>>>(memory, read_attn, write_attn, oW, ob,
                                           out_out, out_mem2, out_wr, out_ww);
}

// round 17
// speedup vs baseline: 1.2088x; 1.2088x over previous
#include <cuda_runtime.h>
#include <math.h>

#define BATCH  2048
#define NROWS  512
#define MDIM   64
#define HDIM   100
#define INDIM  64
#define OUTDIM 64
#define EPS    1e-8f

#define SCR_STRIDE 288
__device__ float g_scratch[(size_t)BATCH * SCR_STRIDE];

__device__ __forceinline__ float softplus_f(float x) {
    return (x > 20.f) ? x : log1pf(expf(x));
}
__device__ __forceinline__ float sigmoid_f(float x) {
    return 1.f / (1.f + expf(-x));
}

__device__ __forceinline__ void cp_async16(void* smem_dst, const void* gmem_src) {
    unsigned s = (unsigned)__cvta_generic_to_shared(smem_dst);
    asm volatile("cp.async.cg.shared.global [%0], [%1], 16;\n" :: "r"(s), "l"(gmem_src));
}
#define CP_COMMIT()  asm volatile("cp.async.commit_group;\n")

// ---------------------------------------------------------------------------
// Kernel 1: head parameters. grid 128 x 576 threads, 16 batches per CTA.
// (R5-proven configuration, unchanged)
// ---------------------------------------------------------------------------
#define P_CW   0
#define P_WH   6400
#define P_RH   13400
#define P_WE   20400
#define P_XS   33200
#define P_HS   34288
#define P_PS   36288
#define P_TOT  40640

__global__ __launch_bounds__(576) void ntm_params_kernel(
    const float* __restrict__ x,  const float* __restrict__ cW,  const float* __restrict__ cb,
    const float* __restrict__ whW, const float* __restrict__ whb,
    const float* __restrict__ weW, const float* __restrict__ web,
    const float* __restrict__ rhW, const float* __restrict__ rhb)
{
    extern __shared__ __align__(16) float psm[];
    float* xs = psm + P_XS;
    float* hs = psm + P_HS;
    float* ps = psm + P_PS;

    const int tid = threadIdx.x;
    const int b0  = blockIdx.x * 16;

    {
        float4* d = (float4*)(psm + P_CW);
        const float4* s = (const float4*)cW;
        for (int k = tid; k < 1600; k += 576) cp_async16(&d[k], &s[k]);
        CP_COMMIT();
    }
    {
        float4* d; const float4* s;
        d = (float4*)(psm + P_WH); s = (const float4*)whW;
        for (int k = tid; k < 1750; k += 576) cp_async16(&d[k], &s[k]);
        d = (float4*)(psm + P_RH); s = (const float4*)rhW;
        for (int k = tid; k < 1750; k += 576) cp_async16(&d[k], &s[k]);
        d = (float4*)(psm + P_WE); s = (const float4*)weW;
        for (int k = tid; k < 3200; k += 576) cp_async16(&d[k], &s[k]);
        CP_COMMIT();
    }

    for (int idx = tid; idx < 16 * 64; idx += 576) {
        int b = idx >> 6, i = idx & 63;
        xs[i * 17 + b] = x[(size_t)(b0 + b) * 64 + i];
    }
    asm volatile("cp.async.wait_group 1;\n");
    __syncthreads();

    for (int idx = tid; idx < 16 * 100; idx += 576) {
        int j = idx % 100, b = idx / 100;
        float acc = cb[j];
        #pragma unroll 8
        for (int i = 0; i < 64; i++) acc = fmaf(xs[i * 17 + b], psm[P_CW + i * 100 + j], acc);
        hs[j * 20 + b] = acc;
    }
    asm volatile("cp.async.wait_group 0;\n");
    __syncthreads();

    {
        int j = -1, bo = 0;
        if (tid < 268)                        { j = tid;       bo = 0; }
        else if (tid >= 288 && tid < 556)     { j = tid - 288; bo = 8; }
        if (j >= 0) {
            const float* W; int stride, jj; float bj;
            if (j < 70)       { W = psm + P_WH; stride = 70;  jj = j;       bj = whb[jj]; }
            else if (j < 140) { W = psm + P_RH; stride = 70;  jj = j - 70;  bj = rhb[jj]; }
            else              { W = psm + P_WE; stride = 128; jj = j - 140; bj = web[jj]; }

            float acc[8];
            #pragma unroll
            for (int b = 0; b < 8; b++) acc[b] = bj;

            #pragma unroll 4
            for (int i = 0; i < HDIM; i++) {
                float w = W[i * stride + jj];
                const float4* hv = (const float4*)(hs + i * 20 + bo);
                float4 h0 = hv[0], h1 = hv[1];
                acc[0] = fmaf(h0.x, w, acc[0]);  acc[1] = fmaf(h0.y, w, acc[1]);
                acc[2] = fmaf(h0.z, w, acc[2]);  acc[3] = fmaf(h0.w, w, acc[3]);
                acc[4] = fmaf(h1.x, w, acc[4]);  acc[5] = fmaf(h1.y, w, acc[5]);
                acc[6] = fmaf(h1.z, w, acc[6]);  acc[7] = fmaf(h1.w, w, acc[7]);
            }
            #pragma unroll
            for (int b = 0; b < 8; b++) ps[(bo + b) * 272 + j] = acc[b];
        }
    }
    __syncthreads();

    for (int idx = tid; idx < 16 * 128; idx += 576) {
        int b = idx >> 7, j = idx & 127;
        float v = ps[b * 272 + 140 + j];
        float* scr = g_scratch + (size_t)(b0 + b) * SCR_STRIDE;
        if (j < 64) scr[128 + j]        = sigmoid_f(v);
        else        scr[192 + (j - 64)] = v;
    }
    for (int idx = tid; idx < 16 * 64; idx += 576) {
        int b = idx >> 6, j = idx & 63;
        float* scr = g_scratch + (size_t)(b0 + b) * SCR_STRIDE;
        scr[j]      = ps[b * 272 + j];
        scr[64 + j] = ps[b * 272 + 70 + j];
    }
    if (tid < 16) {
        const float* pw = ps + tid * 272;
        const float* pr = pw + 70;
        float* scr = g_scratch + (size_t)(b0 + tid) * SCR_STRIDE + 256;
        float ssw = 0.f, ssr = 0.f;
        #pragma unroll 8
        for (int j = 0; j < 64; j++) { ssw = fmaf(pw[j], pw[j], ssw); ssr = fmaf(pr[j], pr[j], ssr); }

        scr[0] = softplus_f(pw[64]);
        scr[1] = sigmoid_f(pw[65]);
        float m  = fmaxf(pw[66], fmaxf(pw[67], pw[68]));
        float e0 = expf(pw[66] - m), e1 = expf(pw[67] - m), e2 = expf(pw[68] - m);
        float s  = e0 + e1 + e2;
        scr[2] = e0 / s; scr[3] = e1 / s; scr[4] = e2 / s;
        scr[5] = 1.f + softplus_f(pw[69]);
        scr[6] = fmaxf(sqrtf(ssw), EPS);

        scr[7] = softplus_f(pr[64]);
        scr[8] = sigmoid_f(pr[65]);
        m  = fmaxf(pr[66], fmaxf(pr[67], pr[68]));
        e0 = expf(pr[66] - m); e1 = expf(pr[67] - m); e2 = expf(pr[68] - m);
        s  = e0 + e1 + e2;
        scr[9] = e0 / s; scr[10] = e1 / s; scr[11] = e2 / s;
        scr[12] = 1.f + softplus_f(pr[69]);
        scr[13] = fmaxf(sqrtf(ssr), EPS);
    }
}

// ---------------------------------------------------------------------------
// One-barrier block sum over 512 threads.
// ---------------------------------------------------------------------------
__device__ __forceinline__ float blockSum512(float v, float* red16) {
    #pragma unroll
    for (int o = 16; o > 0; o >>= 1) v += __shfl_xor_sync(0xffffffffu, v, o);
    if ((threadIdx.x & 31) == 0) red16[threadIdx.x >> 5] = v;
    __syncthreads();
    float s = 0.f;
    #pragma unroll
    for (int i = 0; i < 16; i++) s += red16[i];
    return s;
}

// ---------------------------------------------------------------------------
// Kernel 2: main (R5-proven configuration; micro-opts: __expf + __fdividef).
// One CTA per batch, 512 threads, occ 2.
// Pass 1: cp.async double-buffered 128-row tiles (DRAM stream).
// Prefetch: pass-2 tiles 0,1 issued BEFORE addressing (overlaps the bubble).
// Addressing: smem attn, no-max softmax, 1-barrier reductions, __powf.
// Pass 2: smem-fed double-buffered mem2 write + S1/S2 (no exposed L2 latency).
// ---------------------------------------------------------------------------
#define SMEM_FLOATS (16384 + 4096 + 4096 + 256 + 1536 + 80 + 16 + 64 + 16 + 1024)

__global__ __launch_bounds__(512, 2) void ntm_main_kernel(
    const float* __restrict__ memory, const float* __restrict__ read_attn,
    const float* __restrict__ write_attn, const float* __restrict__ oW,
    const float* __restrict__ ob,
    float* __restrict__ out_out, float* __restrict__ out_mem2,
    float* __restrict__ out_wr,  float* __restrict__ out_ww)
{
    extern __shared__ __align__(16) float sm[];
    float4* bufA  = (float4*)sm;
    float4* bufB  = bufA + 2048;
    float*  part  = sm + 16384;
    float*  mom   = sm + 20480;
    float*  c_kw  = sm + 24576;
    float*  c_kr  = c_kw + 64;
    float*  c_e   = c_kr + 64;
    float*  c_a   = c_e  + 64;
    float*  ww_s  = c_a  + 64;
    float*  wr_s  = ww_s + 512;
    float*  wg_s  = wr_s + 512;
    float*  red   = wg_s + 512;   // 5 x 16
    float*  scal  = red  + 80;
    float*  rs    = scal + 16;
    float*  sc2   = rs   + 64;    // 16
    float*  wa_s  = sc2  + 16;    // 512
    float*  ra_s  = wa_s + 512;   // 512

    const int tid = threadIdx.x;
    const int b   = blockIdx.x;
    const float* mbase = memory + (size_t)b * NROWS * MDIM;

    // ---- prologue: tile0 (+attn) then tile1 --------------------------------
    {
        const float4* src = (const float4*)mbase;
        #pragma unroll
        for (int k = 0; k < 4; k++) {
            int f = tid + k * 512;
            int r = f >> 4, c4 = f & 15;
            cp_async16(&bufA[r * 16 + (c4 ^ (r & 15))], &src[f]);
        }
        if (tid < 128)
            cp_async16(((float4*)wa_s) + tid, ((const float4*)(write_attn + (size_t)b * 512)) + tid);
        else if (tid < 256)
            cp_async16(((float4*)ra_s) + (tid - 128), ((const float4*)(read_attn + (size_t)b * 512)) + (tid - 128));
        CP_COMMIT();
        src += 2048;
        #pragma unroll
        for (int k = 0; k < 4; k++) {
            int f = tid + k * 512;
            int r = f >> 4, c4 = f & 15;
            cp_async16(&bufB[r * 16 + (c4 ^ (r & 15))], &src[f]);
        }
        CP_COMMIT();
    }

    // ---- coefficients -------------------------------------------------------
    {
        const float* scr = g_scratch + (size_t)b * SCR_STRIDE;
        if (tid < 64) {
            c_kw[tid] = scr[tid];
            c_kr[tid] = scr[64 + tid];
            c_e[tid]  = scr[128 + tid];
            c_a[tid]  = scr[192 + tid];
        } else if (tid < 80) {
            scal[tid - 64] = scr[256 + (tid - 64)];
        }
    }
    __syncthreads();
    if (tid < 32) {
        float ka = c_kr[tid] * c_a[tid] + c_kr[tid + 32] * c_a[tid + 32];
        float aa = c_a[tid]  * c_a[tid] + c_a[tid + 32]  * c_a[tid + 32];
        #pragma unroll
        for (int o = 16; o > 0; o >>= 1) {
            ka += __shfl_xor_sync(0xffffffffu, ka, o);
            aa += __shfl_xor_sync(0xffffffffu, aa, o);
        }
        if (tid == 0) { sc2[0] = ka; sc2[1] = aa; }
    }

    // ---- pass 1: moments ----------------------------------------------------
    const int q = tid >> 7, r = tid & 127;
    const float4* kw4 = (const float4*)c_kw;
    const float4* kr4 = (const float4*)c_kr;
    const float4* e4  = (const float4*)c_e;
    const float4* a4  = (const float4*)c_a;

    #pragma unroll 1
    for (int tt = 0; tt < 4; tt++) {
        if (tt < 3) { asm volatile("cp.async.wait_group 1;\n"); }
        else        { asm volatile("cp.async.wait_group 0;\n"); }
        __syncthreads();

        const float4* bt = (tt & 1) ? bufB : bufA;
        float d0 = 0, q0 = 0, d1 = 0, d2 = 0, p1 = 0, p2 = 0, s1 = 0, s2 = 0;
        #pragma unroll
        for (int j = 0; j < 4; j++) {
            int c4 = (q << 2) + j;
            float4 v  = bt[r * 16 + (c4 ^ (r & 15))];
            float4 kw = kw4[c4], kr = kr4[c4], ee = e4[c4], aa4 = a4[c4];
            {
                float vv = v.x, ev = ee.x * vv;
                d0 = fmaf(kw.x, vv, d0);  d1 = fmaf(kr.x, vv, d1);  s1 = fmaf(aa4.x, vv, s1);
                q0 = fmaf(vv, vv, q0);    p1 = fmaf(vv, ev, p1);    p2 = fmaf(ev, ev, p2);
                d2 = fmaf(kr.x, ev, d2);  s2 = fmaf(aa4.x, ev, s2);
            }
            {
                float vv = v.y, ev = ee.y * vv;
                d0 = fmaf(kw.y, vv, d0);  d1 = fmaf(kr.y, vv, d1);  s1 = fmaf(aa4.y, vv, s1);
                q0 = fmaf(vv, vv, q0);    p1 = fmaf(vv, ev, p1);    p2 = fmaf(ev, ev, p2);
                d2 = fmaf(kr.y, ev, d2);  s2 = fmaf(aa4.y, ev, s2);
            }
            {
                float vv = v.z, ev = ee.z * vv;
                d0 = fmaf(kw.z, vv, d0);  d1 = fmaf(kr.z, vv, d1);  s1 = fmaf(aa4.z, vv, s1);
                q0 = fmaf(vv, vv, q0);    p1 = fmaf(vv, ev, p1);    p2 = fmaf(ev, ev, p2);
                d2 = fmaf(kr.z, ev, d2);  s2 = fmaf(aa4.z, ev, s2);
            }
            {
                float vv = v.w, ev = ee.w * vv;
                d0 = fmaf(kw.w, vv, d0);  d1 = fmaf(kr.w, vv, d1);  s1 = fmaf(aa4.w, vv, s1);
                q0 = fmaf(vv, vv, q0);    p1 = fmaf(vv, ev, p1);    p2 = fmaf(ev, ev, p2);
                d2 = fmaf(kr.w, ev, d2);  s2 = fmaf(aa4.w, ev, s2);
            }
        }
        part[0 * 512 + tid] = d0;  part[1 * 512 + tid] = q0;
        part[2 * 512 + tid] = d1;  part[3 * 512 + tid] = d2;
        part[4 * 512 + tid] = p1;  part[5 * 512 + tid] = p2;
        part[6 * 512 + tid] = s1;  part[7 * 512 + tid] = s2;
        __syncthreads();

        if (tt + 2 < 4) {
            float4* dst = (tt & 1) ? bufB : bufA;
            const float4* src = (const float4*)(mbase + (size_t)(tt + 2) * 8192);
            #pragma unroll
            for (int k = 0; k < 4; k++) {
                int f = tid + k * 512;
                int rr = f >> 4, c4 = f & 15;
                cp_async16(&dst[rr * 16 + (c4 ^ (rr & 15))], &src[f]);
            }
            CP_COMMIT();
        }
        if (tid < 128) {
            int n = tt * 128 + tid;
            #pragma unroll
            for (int m = 0; m < 8; m++) {
                float s = part[m * 512 + tid] + part[m * 512 + 128 + tid]
                        + part[m * 512 + 256 + tid] + part[m * 512 + 384 + tid];
                mom[m * 512 + n] = s;
            }
        }
    }

    // ---- prefetch pass-2 tiles 0,1 (overlaps addressing) --------------------
    {
        const float4* src = (const float4*)mbase;
        #pragma unroll
        for (int k = 0; k < 4; k++) {
            int f = tid + k * 512;
            int rr = f >> 4, c4 = f & 15;
            cp_async16(&bufA[rr * 16 + (c4 ^ (rr & 15))], &src[f]);
        }
        CP_COMMIT();
        src += 2048;
        #pragma unroll
        for (int k = 0; k < 4; k++) {
            int f = tid + k * 512;
            int rr = f >> 4, c4 = f & 15;
            cp_async16(&bufB[rr * 16 + (c4 ^ (rr & 15))], &src[f]);
        }
        CP_COMMIT();
    }
    __syncthreads();

    // ---- addressing ---------------------------------------------------------
    const int n = tid;
    const float d0 = mom[n],            q0 = mom[512 + n];
    const float d1 = mom[1024 + n],     d2 = mom[1536 + n];
    const float p1 = mom[2048 + n],     p2 = mom[2560 + n];
    const float t1 = mom[3072 + n],     t2 = mom[3584 + n];

    const float beta_w = scal[0], gate_w = scal[1], shw0 = scal[2], shw1 = scal[3],
                shw2 = scal[4], gamma_w = scal[5], kn_w = scal[6];
    const float beta_r = scal[7], gate_r = scal[8], shr0 = scal[9], shr1 = scal[10],
                shr2 = scal[11], gamma_r = scal[12], kn_r = scal[13];
    const float ka = sc2[0], aa = sc2[1];

    // write head (no max-subtraction: |score| <= beta, safe in fp32)
    float mn = fmaxf(sqrtf(q0), EPS);
    float ex = __expf(beta_w * d0 / (kn_w * mn));
    float sum = blockSum512(ex, red);
    float wc  = __fdividef(ex, sum);
    float wgv = gate_w * wc + (1.f - gate_w) * wa_s[n];
    wg_s[n] = wgv;
    __syncthreads();
    float tw  = shw2 * wg_s[(n + 511) & 511] + shw1 * wgv + shw0 * wg_s[(n + 1) & 511];
    float twg = __powf(tw, gamma_w);
    float tsum = blockSum512(twg, red + 16);
    float ww = __fdividef(twg, EPS + tsum);
    ww_s[n] = ww;
    __stcs(out_ww + (size_t)b * NROWS + n, ww);

    // read head on virtual mem2
    float dot2 = d1 - ww * d2 + ww * ka;
    float ss2  = q0 - 2.f * ww * p1 + ww * ww * p2
               + 2.f * ww * t1 - 2.f * ww * ww * t2 + ww * ww * aa;
    float mn2 = fmaxf(sqrtf(fmaxf(ss2, 0.f)), EPS);
    float ex2 = __expf(beta_r * dot2 / (kn_r * mn2));
    float sum2 = blockSum512(ex2, red + 32);
    float wc2  = __fdividef(ex2, sum2);
    float wgv2 = gate_r * wc2 + (1.f - gate_r) * ra_s[n];
    wg_s[n] = wgv2;
    __syncthreads();
    float tw2  = shr2 * wg_s[(n + 511) & 511] + shr1 * wgv2 + shr0 * wg_s[(n + 1) & 511];
    float twg2 = __powf(tw2, gamma_r);
    float tsum2 = blockSum512(twg2, red + 48);
    float wr = __fdividef(twg2, EPS + tsum2);
    wr_s[n] = wr;
    __stcs(out_wr + (size_t)b * NROWS + n, wr);

    float cwr = blockSum512(wr * ww, red + 64);  // barrier also publishes ww_s/wr_s

    // ---- pass 2: smem-fed mem2 + S1/S2 --------------------------------------
    float* s1p = part;          // 2048 floats
    float* s2p = part + 2048;   // 2048 floats
    {
        const int m4 = tid & 15;
        const float4 em = ((const float4*)c_e)[m4];
        const float4 am = ((const float4*)c_a)[m4];
        float4* m2b4 = (float4*)(out_mem2 + (size_t)b * NROWS * MDIM);

        float4 s1 = make_float4(0.f, 0.f, 0.f, 0.f);
        float4 s2 = make_float4(0.f, 0.f, 0.f, 0.f);

        #pragma unroll 1
        for (int tt = 0; tt < 4; tt++) {
            if (tt < 3) { asm volatile("cp.async.wait_group 1;\n"); }
            else        { asm volatile("cp.async.wait_group 0;\n"); }
            __syncthreads();

            const float4* bt = (tt & 1) ? bufB : bufA;
            #pragma unroll
            for (int k = 0; k < 4; k++) {
                int f  = tid + k * 512;
                int rl = f >> 4, c4 = f & 15;
                int row = tt * 128 + rl;
                float4 v = bt[rl * 16 + (c4 ^ (rl & 15))];
                float wwn = ww_s[row], wrn = wr_s[row];
                float4 m2;
                m2.x = fmaf(v.x, 1.f - wwn * em.x, wwn * am.x);
                m2.y = fmaf(v.y, 1.f - wwn * em.y, wwn * am.y);
                m2.z = fmaf(v.z, 1.f - wwn * em.z, wwn * am.z);
                m2.w = fmaf(v.w, 1.f - wwn * em.w, wwn * am.w);
                __stcs(&m2b4[row * 16 + c4], m2);
                float wrw = wrn * wwn;
                s1.x = fmaf(wrn, v.x, s1.x);  s2.x = fmaf(wrw, v.x, s2.x);
                s1.y = fmaf(wrn, v.y, s1.y);  s2.y = fmaf(wrw, v.y, s2.y);
                s1.z = fmaf(wrn, v.z, s1.z);  s2.z = fmaf(wrw, v.z, s2.z);
                s1.w = fmaf(wrn, v.w, s1.w);  s2.w = fmaf(wrw, v.w, s2.w);
            }
            __syncthreads();   // buffer consumed before refill

            if (tt + 2 < 4) {
                float4* dst = (tt & 1) ? bufB : bufA;
                const float4* src = (const float4*)(mbase + (size_t)(tt + 2) * 8192);
                #pragma unroll
                for (int k = 0; k < 4; k++) {
                    int f = tid + k * 512;
                    int rr = f >> 4, c4 = f & 15;
                    cp_async16(&dst[rr * 16 + (c4 ^ (rr & 15))], &src[f]);
                }
                CP_COMMIT();
            }
        }
        ((float4*)s1p)[tid] = s1;   // layout [g=tid>>4][m]
        ((float4*)s2p)[tid] = s2;
    }
    __syncthreads();

    if (tid < 64) {
        float r1 = 0.f, r2 = 0.f;
        #pragma unroll
        for (int g = 0; g < 32; g++) { r1 += s1p[g * 64 + tid]; r2 += s2p[g * 64 + tid]; }
        rs[tid] = r1 - c_e[tid] * r2 + cwr * c_a[tid];
    }
    __syncthreads();

    if (tid < 64) {
        float acc = ob[tid];
        #pragma unroll 8
        for (int m = 0; m < 64; m++) acc = fmaf(rs[m], oW[m * 64 + tid], acc);
        out_out[(size_t)b * OUTDIM + tid] = sigmoid_f(acc);
    }
}

// ---------------------------------------------------------------------------
extern "C" void kernel_launch(void* const* d_in, const int* in_sizes, int n_in,
                              void* d_out, int out_size)
{
    const float* x          = (const float*)d_in[0];
    const float* memory     = (const float*)d_in[1];
    const float* read_attn  = (const float*)d_in[2];
    const float* write_attn = (const float*)d_in[3];
    const float* cW         = (const float*)d_in[4];
    const float* cb         = (const float*)d_in[5];
    const float* oW         = (const float*)d_in[6];
    const float* ob         = (const float*)d_in[7];
    const float* whW        = (const float*)d_in[8];
    const float* whb        = (const float*)d_in[9];
    const float* weW        = (const float*)d_in[10];
    const float* web        = (const float*)d_in[11];
    const float* rhW        = (const float*)d_in[12];
    const float* rhb        = (const float*)d_in[13];

    float* out_out  = (float*)d_out;
    float* out_mem2 = out_out  + (size_t)BATCH * OUTDIM;
    float* out_wr   = out_mem2 + (size_t)BATCH * NROWS * MDIM;
    float* out_ww   = out_wr   + (size_t)BATCH * NROWS;

    const int smemP = P_TOT * (int)sizeof(float);
    const int smemB = SMEM_FLOATS * (int)sizeof(float);
    cudaFuncSetAttribute(ntm_params_kernel,
                         cudaFuncAttributeMaxDynamicSharedMemorySize, smemP);
    cudaFuncSetAttribute(ntm_main_kernel,
                         cudaFuncAttributeMaxDynamicSharedMemorySize, smemB);

    ntm_params_kernel<<<BATCH / 16, 576, smemP>>>(x, cW, cb, whW, whb, weW, web, rhW, rhb);
    ntm_main_kernel<<<BATCH, 512, smemB>>>(memory, read_attn, write_attn, oW, ob,
                                           out_out, out_mem2, out_wr, out_ww);
}